// round 16
// baseline (speedup 1.0000x reference)
#include <cuda_runtime.h>
#include <cuda_fp16.h>
#include <cstdint>
#include <math.h>

// Fixed shapes: B=4, S=4096, D=1024, WINDOW=128, stride 64
#define BB   4
#define SS   4096
#define DD   1024
#define NW   63
#define MM   (BB*SS)         // 16384
#define BSD  (BB*SS*DD)      // 16,777,216

typedef __half fp16;

// ---------------- scratch (device globals; no allocation allowed) ----------
__device__ fp16 g_qh[BSD]; __device__ fp16 g_ql[BSD];
__device__ fp16 g_kh[BSD];
__device__ fp16 g_vh[BSD];
__device__ fp16 g_xh[BSD]; __device__ fp16 g_xl[BSD];
__device__ fp16 g_wth[4][DD*DD];    // transposed weights hi [N,K]
__device__ float g_E[BSD];
__device__ float g_O[BSD];

// ---------------- helpers ----------------------------------------------------
__device__ __forceinline__ uint32_t smem_u32(const void* p) {
    uint32_t a;
    asm("{ .reg .u64 t; cvta.to.shared.u64 t, %1; cvt.u32.u64 %0, t; }" : "=r"(a) : "l"(p));
    return a;
}
__device__ __forceinline__ float ex2(float x) {
    float y; asm("ex2.approx.f32 %0, %1;" : "=f"(y) : "f"(x)); return y;
}

#define SW128(off) ((off) ^ (((off) >> 3) & 0x70))

#define CP16(dst, src) \
    asm volatile("cp.async.cg.shared.global [%0], [%1], 16;" \
        :: "r"(dst), "l"(__cvta_generic_to_global(src)) : "memory")

#define LDSM_X4(r, a) \
    asm volatile("ldmatrix.sync.aligned.m8n8.x4.shared.b16 {%0,%1,%2,%3}, [%4];" \
        : "=r"((r)[0]), "=r"((r)[1]), "=r"((r)[2]), "=r"((r)[3]) : "r"(a))

#define LDSM_X4T(r, a) \
    asm volatile("ldmatrix.sync.aligned.m8n8.x4.trans.shared.b16 {%0,%1,%2,%3}, [%4];" \
        : "=r"((r)[0]), "=r"((r)[1]), "=r"((r)[2]), "=r"((r)[3]) : "r"(a))

#define MMA16816(c, a, b0, b1) \
    asm volatile("mma.sync.aligned.m16n8k16.row.col.f32.f16.f16.f32 " \
        "{%0,%1,%2,%3}, {%4,%5,%6,%7}, {%8,%9}, {%0,%1,%2,%3};" \
        : "+f"((c)[0]), "+f"((c)[1]), "+f"((c)[2]), "+f"((c)[3]) \
        : "r"((a)[0]), "r"((a)[1]), "r"((a)[2]), "r"((a)[3]), "r"(b0), "r"(b1))

__device__ __forceinline__ uint32_t pk2h(fp16 a, fp16 b) {
    __half2 t = __halves2half2(a, b);
    return *reinterpret_cast<uint32_t*>(&t);
}
__device__ __forceinline__ void split1(float v, fp16 &h, fp16 &l) {
    h = __float2half_rn(v);
    l = __float2half_rn(v - __half2float(h));
}

// ---------------- small kernels ---------------------------------------------
__global__ void split_x(const float4* __restrict__ in, uint2* __restrict__ hi,
                        uint2* __restrict__ lo, int n4) {
    int i = blockIdx.x * blockDim.x + threadIdx.x;
    int st = gridDim.x * blockDim.x;
    for (; i < n4; i += st) {
        float4 v = in[i];
        fp16 h0,h1,h2,h3,l0,l1,l2,l3;
        split1(v.x,h0,l0); split1(v.y,h1,l1); split1(v.z,h2,l2); split1(v.w,h3,l3);
        hi[i] = make_uint2(pk2h(h0,h1), pk2h(h2,h3));
        lo[i] = make_uint2(pk2h(l0,l1), pk2h(l2,l3));
    }
}

// 4 weight transposes in one launch: W[K,N] fp32 -> Wt[N,K] fp16 (z = which W)
__global__ void transpose_h4(const float* __restrict__ W0, const float* __restrict__ W1,
                             const float* __restrict__ W2, const float* __restrict__ W3,
                             fp16* __restrict__ hi) {
    __shared__ float tl[32][33];
    const float* W = (blockIdx.z == 0) ? W0 : (blockIdx.z == 1) ? W1
                   : (blockIdx.z == 2) ? W2 : W3;
    fp16* out = hi + (long)blockIdx.z * DD * DD;
    int bx = blockIdx.x * 32, by = blockIdx.y * 32;
    int tx = threadIdx.x, ty = threadIdx.y;
#pragma unroll
    for (int r = 0; r < 32; r += 8)
        tl[ty + r][tx] = W[(long)(by + ty + r) * DD + bx + tx];
    __syncthreads();
#pragma unroll
    for (int r = 0; r < 32; r += 8)
        out[(long)(bx + ty + r) * DD + by + tx] = __float2half_rn(tl[tx][ty + r]);
}

// ---------------- shared GEMM constants ---------------------------------------
// Warp grid 4x2, warp tile 32x64: 8 LDSM per 32 MMA.
#define GEMM_SMEM 98304

// ---------------- merged QKV GEMM: gridDim.z = 3 selects Q/K/V ---------------
// Q (which==0): 2 passes (Ah+Al). K/V: 1 pass (outputs fp16-rounded anyway).
__global__ void __launch_bounds__(256, 2) gemm_qkv(
    const fp16* __restrict__ Ah, const fp16* __restrict__ Al,
    const fp16* __restrict__ Wt,
    const float* __restrict__ bq, const float* __restrict__ bk,
    const float* __restrict__ bv,
    fp16* __restrict__ Qhi, fp16* __restrict__ Qlo,
    fp16* __restrict__ Khi, fp16* __restrict__ Vhi)
{
    extern __shared__ char smem[];
    const uint32_t sb = smem_u32(smem);
    const int t = threadIdx.x;
    const int lane = t & 31, wid = t >> 5;
    const int wrow = wid & 3;
    const int wcol = wid >> 2;
    const int which = blockIdx.z;
    const long m0 = (long)blockIdx.y * 128;
    const int  n0 = blockIdx.x * 128;
    const fp16* Bh = Wt + (long)which * DD * DD;
    const int npass = (which == 0) ? 2 : 1;

    const uint32_t sAh[2] = { sb,         sb + 16384 };
    const uint32_t sAl[2] = { sb + 32768, sb + 49152 };
    const uint32_t sB[2]  = { sb + 65536, sb + 81920 };

    int rowg[4]; uint32_t dsts[4];
#pragma unroll
    for (int i = 0; i < 4; i++) {
        int u = t + 256 * i;
        rowg[i] = u >> 3;
        dsts[i] = SW128((u >> 3) * 128 + (u & 7) * 16);
    }
    const int kcol8 = (t & 7) * 8;

    uint32_t a_rowoff[2], a_swz[2];
#pragma unroll
    for (int ms = 0; ms < 2; ms++) {
        int row = wrow * 32 + ms * 16 + (lane & 15);
        a_rowoff[ms] = row * 128;
        a_swz[ms]    = (row & 7) * 16;
    }
    const uint32_t a_kext = (lane >> 4) * 16;
    uint32_t b_rowoff[4], b_swz[4];
#pragma unroll
    for (int np = 0; np < 4; np++) {
        int row = wcol * 64 + np * 16 + ((lane >> 4) & 1) * 8 + (lane & 7);
        b_rowoff[np] = row * 128;
        b_swz[np]    = (row & 7) * 16;
    }
    const uint32_t b_kext = ((lane >> 3) & 1) * 16;

    float acc[2][8][4];
#pragma unroll
    for (int i = 0; i < 2; i++)
#pragma unroll
        for (int j = 0; j < 8; j++)
#pragma unroll
            for (int r = 0; r < 4; r++) acc[i][j][r] = 0.f;

    auto load_chunk = [&](int c, int buf) {
        int kc = c * 64;
        const fp16* Abh = Ah + kc + kcol8;
        const fp16* Bb  = Bh + kc + kcol8;
#pragma unroll
        for (int i = 0; i < 4; i++) CP16(sAh[buf] + dsts[i], Abh + (m0 + rowg[i]) * DD);
        if (which == 0) {
            const fp16* Abl = Al + kc + kcol8;
#pragma unroll
            for (int i = 0; i < 4; i++) CP16(sAl[buf] + dsts[i], Abl + (m0 + rowg[i]) * DD);
        }
#pragma unroll
        for (int i = 0; i < 4; i++) CP16(sB[buf]  + dsts[i], Bb  + (long)(n0 + rowg[i]) * DD);
        asm volatile("cp.async.commit_group;" ::: "memory");
    };

    load_chunk(0, 0);

    for (int c = 0; c < 16; c++) {
        const int buf = c & 1;
        asm volatile("cp.async.wait_group 0;" ::: "memory");
        __syncthreads();
        if (c + 1 < 16) load_chunk(c + 1, buf ^ 1);

#pragma unroll
        for (int k16 = 0; k16 < 4; k16++) {
            const uint32_t kb = k16 * 32;
            uint32_t bfr[4][4];
#pragma unroll
            for (int np = 0; np < 4; np++)
                LDSM_X4(bfr[np], sB[buf] + b_rowoff[np] + ((kb + b_kext) ^ b_swz[np]));
            for (int pass = 0; pass < npass; pass++) {
                const uint32_t bA = pass ? sAl[buf] : sAh[buf];
                uint32_t afr[2][4];
#pragma unroll
                for (int ms = 0; ms < 2; ms++)
                    LDSM_X4(afr[ms], bA + a_rowoff[ms] + ((kb + a_kext) ^ a_swz[ms]));
#pragma unroll
                for (int ms = 0; ms < 2; ms++)
#pragma unroll
                    for (int ns = 0; ns < 8; ns++)
                        MMA16816(acc[ms][ns], afr[ms],
                                 bfr[ns >> 1][(ns & 1) * 2], bfr[ns >> 1][(ns & 1) * 2 + 1]);
            }
        }
    }

    const float* bias = (which == 0) ? bq : (which == 1) ? bk : bv;
#pragma unroll
    for (int ms = 0; ms < 2; ms++) {
        long r0 = m0 + wrow * 32 + ms * 16 + (lane >> 2);
#pragma unroll
        for (int ns = 0; ns < 8; ns++) {
            int col = n0 + wcol * 64 + ns * 8 + (lane & 3) * 2;
            float2 bvv = *(const float2*)(bias + col);
            float v00 = acc[ms][ns][0] + bvv.x, v01 = acc[ms][ns][1] + bvv.y;
            float v10 = acc[ms][ns][2] + bvv.x, v11 = acc[ms][ns][3] + bvv.y;
            if (which == 0) {
                fp16 h0,h1,l0,l1;
                split1(v00, h0, l0); split1(v01, h1, l1);
                *(uint32_t*)(Qhi + r0 * DD + col) = pk2h(h0, h1);
                *(uint32_t*)(Qlo + r0 * DD + col) = pk2h(l0, l1);
                split1(v10, h0, l0); split1(v11, h1, l1);
                *(uint32_t*)(Qhi + (r0 + 8) * DD + col) = pk2h(h0, h1);
                *(uint32_t*)(Qlo + (r0 + 8) * DD + col) = pk2h(l0, l1);
            } else {
                fp16* dst = (which == 1) ? Khi : Vhi;
                *(uint32_t*)(dst + r0 * DD + col) =
                    pk2h(__float2half_rn(v00), __float2half_rn(v01));
                *(uint32_t*)(dst + (r0 + 8) * DD + col) =
                    pk2h(__float2half_rn(v10), __float2half_rn(v11));
            }
        }
    }
}

// ---------------- final AO GEMM, combine fused into A-load --------------------
// A = ((E + O) * countscale) split to fp16 hi/lo ON THE FLY (same math as the
// old combine_split, bit-identical operands). B via cp.async as before.
__global__ void __launch_bounds__(256, 2) gemm_fin(
    const float* __restrict__ E, const float* __restrict__ O,
    const fp16* __restrict__ Bh,
    const float* __restrict__ bias, float* __restrict__ C)
{
    extern __shared__ char smem[];
    const uint32_t sb = smem_u32(smem);
    const int t = threadIdx.x;
    const int lane = t & 31, wid = t >> 5;
    const int wrow = wid & 3;
    const int wcol = wid >> 2;
    const long m0 = (long)blockIdx.y * 128;
    const int  n0 = blockIdx.x * 128;

    const uint32_t sAh[2] = { sb,         sb + 16384 };
    const uint32_t sAl[2] = { sb + 32768, sb + 49152 };
    const uint32_t sB[2]  = { sb + 65536, sb + 81920 };
    const uint32_t rAh[2] = { 0u, 16384u };
    const uint32_t rAl[2] = { 32768u, 49152u };

    // B cp.async targets
    int rowg[4]; uint32_t dsts[4];
#pragma unroll
    for (int i = 0; i < 4; i++) {
        int u = t + 256 * i;
        rowg[i] = u >> 3;
        dsts[i] = SW128((u >> 3) * 128 + (u & 7) * 16);
    }
    const int kcol8 = (t & 7) * 8;

    uint32_t a_rowoff[2], a_swz[2];
#pragma unroll
    for (int ms = 0; ms < 2; ms++) {
        int row = wrow * 32 + ms * 16 + (lane & 15);
        a_rowoff[ms] = row * 128;
        a_swz[ms]    = (row & 7) * 16;
    }
    const uint32_t a_kext = (lane >> 4) * 16;
    uint32_t b_rowoff[4], b_swz[4];
#pragma unroll
    for (int np = 0; np < 4; np++) {
        int row = wcol * 64 + np * 16 + ((lane >> 4) & 1) * 8 + (lane & 7);
        b_rowoff[np] = row * 128;
        b_swz[np]    = (row & 7) * 16;
    }
    const uint32_t b_kext = ((lane >> 3) & 1) * 16;

    float acc[2][8][4];
#pragma unroll
    for (int i = 0; i < 2; i++)
#pragma unroll
        for (int j = 0; j < 8; j++)
#pragma unroll
            for (int r = 0; r < 4; r++) acc[i][j][r] = 0.f;

    auto load_B = [&](int c, int buf) {
        const fp16* Bb = Bh + c * 64 + kcol8;
#pragma unroll
        for (int i = 0; i < 4; i++) CP16(sB[buf] + dsts[i], Bb + (long)(n0 + rowg[i]) * DD);
        asm volatile("cp.async.commit_group;" ::: "memory");
    };

    // convert one float4 slot j (0..7) of chunk c into A buffers
    auto conv_slot = [&](int j, int c, int buf, float4 e, float4 o, bool edge) {
        int u = t + 256 * j;
        int arow = u >> 4, af4 = u & 15;
        float sc = edge ? 1.f : 0.5f;
        if (edge) o = make_float4(0.f, 0.f, 0.f, 0.f);
        float4 v = make_float4((e.x + o.x) * sc, (e.y + o.y) * sc,
                               (e.z + o.z) * sc, (e.w + o.w) * sc);
        fp16 h0,h1,h2,h3,l0,l1,l2,l3;
        split1(v.x,h0,l0); split1(v.y,h1,l1); split1(v.z,h2,l2); split1(v.w,h3,l3);
        uint32_t sw = SW128((uint32_t)(arow * 128 + af4 * 8));
        *(uint2*)(smem + rAh[buf] + sw) = make_uint2(pk2h(h0,h1), pk2h(h2,h3));
        *(uint2*)(smem + rAl[buf] + sw) = make_uint2(pk2h(l0,l1), pk2h(l2,l3));
    };
    auto slot_addr = [&](int j, int c, bool &edge) -> long {
        int u = t + 256 * j;
        int arow = u >> 4, af4 = u & 15;
        long m = m0 + arow;
        int s = (int)(m & (SS - 1));
        edge = (s < 64) || (s >= SS - 64);
        return m * DD + c * 64 + af4 * 4;
    };

    // prologue: convert chunk 0 A, issue B chunk 0
    load_B(0, 0);
#pragma unroll
    for (int j = 0; j < 8; j++) {
        bool edge; long gi = slot_addr(j, 0, edge);
        float4 e = *(const float4*)(E + gi);
        float4 o = edge ? make_float4(0.f,0.f,0.f,0.f) : *(const float4*)(O + gi);
        conv_slot(j, 0, 0, e, o, edge);
    }

    for (int c = 0; c < 16; c++) {
        const int buf = c & 1;
        asm volatile("cp.async.wait_group 0;" ::: "memory");
        __syncthreads();
        if (c + 1 < 16) load_B(c + 1, buf ^ 1);

#pragma unroll
        for (int k16 = 0; k16 < 4; k16++) {
            // prefetch A-conversion batch (2 slots) for chunk c+1
            float4 e0, o0, e1, o1;
            bool ed0 = false, ed1 = false;
            if (c + 1 < 16) {
                long g0 = slot_addr(2*k16,     c + 1, ed0);
                long g1 = slot_addr(2*k16 + 1, c + 1, ed1);
                e0 = *(const float4*)(E + g0);
                o0 = ed0 ? make_float4(0.f,0.f,0.f,0.f) : *(const float4*)(O + g0);
                e1 = *(const float4*)(E + g1);
                o1 = ed1 ? make_float4(0.f,0.f,0.f,0.f) : *(const float4*)(O + g1);
            }

            const uint32_t kb = k16 * 32;
            uint32_t bfr[4][4];
#pragma unroll
            for (int np = 0; np < 4; np++)
                LDSM_X4(bfr[np], sB[buf] + b_rowoff[np] + ((kb + b_kext) ^ b_swz[np]));
#pragma unroll
            for (int pass = 0; pass < 2; pass++) {
                const uint32_t bA = pass ? sAl[buf] : sAh[buf];
                uint32_t afr[2][4];
#pragma unroll
                for (int ms = 0; ms < 2; ms++)
                    LDSM_X4(afr[ms], bA + a_rowoff[ms] + ((kb + a_kext) ^ a_swz[ms]));
#pragma unroll
                for (int ms = 0; ms < 2; ms++)
#pragma unroll
                    for (int ns = 0; ns < 8; ns++)
                        MMA16816(acc[ms][ns], afr[ms],
                                 bfr[ns >> 1][(ns & 1) * 2], bfr[ns >> 1][(ns & 1) * 2 + 1]);
            }

            if (c + 1 < 16) {
                conv_slot(2*k16,     c + 1, buf ^ 1, e0, o0, ed0);
                conv_slot(2*k16 + 1, c + 1, buf ^ 1, e1, o1, ed1);
            }
        }
    }

#pragma unroll
    for (int ms = 0; ms < 2; ms++) {
        long r0 = m0 + wrow * 32 + ms * 16 + (lane >> 2);
#pragma unroll
        for (int ns = 0; ns < 8; ns++) {
            int col = n0 + wcol * 64 + ns * 8 + (lane & 3) * 2;
            float2 bv = *(const float2*)(bias + col);
            *(float2*)(C + r0 * DD + col) =
                make_float2(acc[ms][ns][0] + bv.x, acc[ms][ns][1] + bv.y);
            *(float2*)(C + (r0 + 8) * DD + col) =
                make_float2(acc[ms][ns][2] + bv.x, acc[ms][ns][3] + bv.y);
        }
    }
}

// ---------------- windowed attention (R13-proven form, FROZEN) ---------------
#define ATT_PHI   32768
#define ATT_PLO   65536
#define ATT_RED   98304
#define ATT_SMEM  100352

__global__ void __launch_bounds__(256, 2) window_attn_mma(
    const fp16* __restrict__ qh, const fp16* __restrict__ ql,
    const fp16* __restrict__ kh, const fp16* __restrict__ vh,
    float* __restrict__ Ebuf, float* __restrict__ Obuf)
{
    extern __shared__ char smem[];
    const uint32_t sb = smem_u32(smem);
    const int t = threadIdx.x;
    const int lane = t & 31, wid = t >> 5;
    const int wrow = wid & 1;
    const int wcol = wid >> 1;
    const int w = blockIdx.x, b = blockIdx.y;
    const long qbase = ((long)b * SS + w * 64) * DD;

    const uint32_t sQh[2] = { sb,         sb + 16384 };
    const uint32_t sQl[2] = { sb + 32768, sb + 49152 };
    const uint32_t sK[2]  = { sb + 65536, sb + 81920 };
    const uint32_t vbf[2] = { sb,         sb + 16384 };

    int rowg[4]; uint32_t dsts[4];
#pragma unroll
    for (int i = 0; i < 4; i++) {
        int u = t + 256 * i;
        rowg[i] = u >> 3;
        dsts[i] = SW128((u >> 3) * 128 + (u & 7) * 16);
    }
    const int kcol8 = (t & 7) * 8;

    uint32_t a_rowoff[4], a_swz[4];
#pragma unroll
    for (int ms = 0; ms < 4; ms++) {
        int row = wrow * 64 + ms * 16 + (lane & 15);
        a_rowoff[ms] = row * 128;
        a_swz[ms]    = (row & 7) * 16;
    }
    const uint32_t a_kext = (lane >> 4) * 16;
    uint32_t b_rowoff[2], b_swz[2];
#pragma unroll
    for (int np = 0; np < 2; np++) {
        int row = wcol * 32 + np * 16 + ((lane >> 4) & 1) * 8 + (lane & 7);
        b_rowoff[np] = row * 128;
        b_swz[np]    = (row & 7) * 16;
    }
    const uint32_t b_kext = ((lane >> 3) & 1) * 16;

    float acc[4][4][4];
#pragma unroll
    for (int i = 0; i < 4; i++)
#pragma unroll
        for (int j = 0; j < 4; j++)
#pragma unroll
            for (int r = 0; r < 4; r++) acc[i][j][r] = 0.f;

    auto load_qk = [&](int c, int buf) {
        int kc = c * 64;
        const fp16* Abh = qh + qbase + kc + kcol8;
        const fp16* Abl = ql + qbase + kc + kcol8;
        const fp16* Bb  = kh + qbase + kc + kcol8;
#pragma unroll
        for (int i = 0; i < 4; i++) CP16(sQh[buf] + dsts[i], Abh + (long)rowg[i] * DD);
#pragma unroll
        for (int i = 0; i < 4; i++) CP16(sQl[buf] + dsts[i], Abl + (long)rowg[i] * DD);
#pragma unroll
        for (int i = 0; i < 4; i++) CP16(sK[buf]  + dsts[i], Bb  + (long)rowg[i] * DD);
        asm volatile("cp.async.commit_group;" ::: "memory");
    };

    load_qk(0, 0);

    for (int c = 0; c < 16; c++) {
        const int buf = c & 1;
        asm volatile("cp.async.wait_group 0;" ::: "memory");
        __syncthreads();
        if (c + 1 < 16) load_qk(c + 1, buf ^ 1);

#pragma unroll
        for (int k16 = 0; k16 < 4; k16++) {
            const uint32_t kb = k16 * 32;
            uint32_t bfr[2][4];
#pragma unroll
            for (int np = 0; np < 2; np++)
                LDSM_X4(bfr[np], sK[buf] + b_rowoff[np] + ((kb + b_kext) ^ b_swz[np]));
#pragma unroll
            for (int pass = 0; pass < 2; pass++) {
                const uint32_t bA = pass ? sQl[buf] : sQh[buf];
                uint32_t afr[4][4];
#pragma unroll
                for (int ms = 0; ms < 4; ms++)
                    LDSM_X4(afr[ms], bA + a_rowoff[ms] + ((kb + a_kext) ^ a_swz[ms]));
#pragma unroll
                for (int ms = 0; ms < 4; ms++)
#pragma unroll
                    for (int ns = 0; ns < 4; ns++)
                        MMA16816(acc[ms][ns], afr[ms],
                                 bfr[ns >> 1][(ns & 1) * 2], bfr[ns >> 1][(ns & 1) * 2 + 1]);
            }
        }
    }

    auto load_v = [&](int nc, int buf) {
        const fp16* Vh = vh + qbase + nc * 64 + kcol8;
#pragma unroll
        for (int i = 0; i < 4; i++) CP16(vbf[buf] + dsts[i], Vh + (long)rowg[i] * DD);
        asm volatile("cp.async.commit_group;" ::: "memory");
    };
    load_v(0, 0);

    const float CEXP = 0.1803368801f;
    float* red = (float*)(smem + ATT_RED);
    float ps[4][2];
#pragma unroll
    for (int ms = 0; ms < 4; ms++) {
        ps[ms][0] = 0.f; ps[ms][1] = 0.f;
#pragma unroll
        for (int ns = 0; ns < 4; ns++) {
#pragma unroll
            for (int r = 0; r < 4; r++) {
                float e = ex2(acc[ms][ns][r] * CEXP);
                acc[ms][ns][r] = e;
                ps[ms][r >> 1] += e;
            }
        }
    }
#pragma unroll
    for (int off = 1; off < 4; off <<= 1)
#pragma unroll
        for (int ms = 0; ms < 4; ms++) {
            ps[ms][0] += __shfl_xor_sync(0xffffffffu, ps[ms][0], off);
            ps[ms][1] += __shfl_xor_sync(0xffffffffu, ps[ms][1], off);
        }
    if ((lane & 3) == 0) {
#pragma unroll
        for (int ms = 0; ms < 4; ms++)
#pragma unroll
            for (int h = 0; h < 2; h++) {
                int row = wrow * 64 + ms * 16 + (lane >> 2) + h * 8;
                red[wcol * 128 + row] = ps[ms][h];
            }
    }
    __syncthreads();

#pragma unroll
    for (int ms = 0; ms < 4; ms++) {
#pragma unroll
        for (int h = 0; h < 2; h++) {
            int row = wrow * 64 + ms * 16 + (lane >> 2) + h * 8;
            float s = red[row] + red[128 + row] + red[256 + row] + red[384 + row];
            float inv = 1.f / s;
#pragma unroll
            for (int ns = 0; ns < 4; ns++) {
                int col = wcol * 32 + ns * 8 + (lane & 3) * 2;
                float p0 = acc[ms][ns][h * 2]     * inv;
                float p1 = acc[ms][ns][h * 2 + 1] * inv;
                fp16 h0, l0, h1, l1;
                split1(p0, h0, l0); split1(p1, h1, l1);
                uint32_t off = (col >> 6) * 16384 + SW128(row * 128 + (col & 63) * 2);
                *(uint32_t*)(smem + ATT_PHI + off) = pk2h(h0, h1);
                *(uint32_t*)(smem + ATT_PLO + off) = pk2h(l0, l1);
            }
        }
    }
    __syncthreads();

    const int r0v = (lane & 7) + ((lane >> 3) & 1) * 8;
    const uint32_t b2_row = (uint32_t)r0v * 128;
    const uint32_t b2_cs  = ((wcol * 16 + (lane >> 4) * 8) * 2) ^ ((r0v & 7) * 16);

    float* dst = (w & 1) ? Obuf : Ebuf;
    const long rowbase = (long)b * SS + w * 64 + wrow * 64;

    for (int nc = 0; nc < 16; nc++) {
        const int buf = nc & 1;
        asm volatile("cp.async.wait_group 0;" ::: "memory");
        __syncthreads();
        if (nc + 1 < 16) load_v(nc + 1, buf ^ 1);

        float acc2[4][2][4];
#pragma unroll
        for (int i = 0; i < 4; i++)
#pragma unroll
            for (int j = 0; j < 2; j++)
#pragma unroll
                for (int r = 0; r < 4; r++) acc2[i][j][r] = 0.f;

#pragma unroll
        for (int k16 = 0; k16 < 8; k16++) {
            const uint32_t pchunk = (k16 >> 2) * 16384;
            const uint32_t kb = (k16 & 3) * 32;
            uint32_t bfr[4];
            LDSM_X4T(bfr, vbf[buf] + b2_row + (uint32_t)k16 * 2048 + b2_cs);
#pragma unroll
            for (int pass = 0; pass < 2; pass++) {
                const uint32_t Pb = sb + (pass ? ATT_PLO : ATT_PHI);
                uint32_t afr[4][4];
#pragma unroll
                for (int ms = 0; ms < 4; ms++)
                    LDSM_X4(afr[ms], Pb + pchunk + a_rowoff[ms] + ((kb + a_kext) ^ a_swz[ms]));
#pragma unroll
                for (int ms = 0; ms < 4; ms++) {
                    MMA16816(acc2[ms][0], afr[ms], bfr[0], bfr[1]);
                    MMA16816(acc2[ms][1], afr[ms], bfr[2], bfr[3]);
                }
            }
        }

#pragma unroll
        for (int ms = 0; ms < 4; ms++) {
#pragma unroll
            for (int h = 0; h < 2; h++) {
                long s = rowbase + ms * 16 + (lane >> 2) + h * 8;
#pragma unroll
                for (int ns = 0; ns < 2; ns++) {
                    int col = nc * 64 + wcol * 16 + ns * 8 + (lane & 3) * 2;
                    *(float2*)(dst + s * DD + col) =
                        make_float2(acc2[ms][ns][h * 2], acc2[ms][ns][h * 2 + 1]);
                }
            }
        }
    }
}

// ---------------- launch -----------------------------------------------------
extern "C" void kernel_launch(void* const* d_in, const int* in_sizes, int n_in,
                              void* d_out, int out_size)
{
    const float* x  = (const float*)d_in[0];
    const float* Wq = (const float*)d_in[1];
    const float* bq = (const float*)d_in[2];
    const float* Wk = (const float*)d_in[3];
    const float* bk = (const float*)d_in[4];
    const float* Wv = (const float*)d_in[5];
    const float* bv = (const float*)d_in[6];
    const float* Wo = (const float*)d_in[7];
    const float* bo = (const float*)d_in[8];
    float* out = (float*)d_out;

    fp16 *qh,*ql,*kh,*vh,*xh,*xl,*wth;
    float *E, *O;
    cudaGetSymbolAddress((void**)&qh, g_qh); cudaGetSymbolAddress((void**)&ql, g_ql);
    cudaGetSymbolAddress((void**)&kh, g_kh);
    cudaGetSymbolAddress((void**)&vh, g_vh);
    cudaGetSymbolAddress((void**)&xh, g_xh); cudaGetSymbolAddress((void**)&xl, g_xl);
    cudaGetSymbolAddress((void**)&wth, g_wth);
    cudaGetSymbolAddress((void**)&E, g_E); cudaGetSymbolAddress((void**)&O, g_O);

    cudaFuncSetAttribute(gemm_qkv, cudaFuncAttributeMaxDynamicSharedMemorySize, GEMM_SMEM);
    cudaFuncSetAttribute(gemm_fin, cudaFuncAttributeMaxDynamicSharedMemorySize, GEMM_SMEM);
    cudaFuncSetAttribute(window_attn_mma, cudaFuncAttributeMaxDynamicSharedMemorySize, ATT_SMEM);

    transpose_h4<<<dim3(32, 32, 4), dim3(32, 8)>>>(Wq, Wk, Wv, Wo, wth);
    split_x<<<2048, 256>>>((const float4*)x, (uint2*)xh, (uint2*)xl, BSD / 4);

    gemm_qkv<<<dim3(DD / 128, MM / 128, 3), 256, GEMM_SMEM>>>(
        xh, xl, wth, bq, bk, bv, qh, ql, kh, vh);

    window_attn_mma<<<dim3(NW, BB), 256, ATT_SMEM>>>(qh, ql, kh, vh, E, O);

    gemm_fin<<<dim3(DD / 128, MM / 128), 256, GEMM_SMEM>>>(E, O, wth + 3L*DD*DD, bo, out);
}

// round 17
// speedup vs baseline: 1.1740x; 1.1740x over previous
#include <cuda_runtime.h>
#include <cuda_fp16.h>
#include <cstdint>
#include <math.h>

// Fixed shapes: B=4, S=4096, D=1024, WINDOW=128, stride 64
#define BB   4
#define SS   4096
#define DD   1024
#define NW   63
#define MM   (BB*SS)         // 16384
#define BSD  (BB*SS*DD)      // 16,777,216

typedef __half fp16;

// ---------------- scratch (device globals; no allocation allowed) ----------
__device__ fp16 g_qh[BSD]; __device__ fp16 g_ql[BSD];
__device__ fp16 g_kh[BSD];
__device__ fp16 g_vh[BSD];
__device__ fp16 g_xh[BSD]; __device__ fp16 g_xl[BSD];
__device__ fp16 g_ah[BSD];
__device__ fp16 g_wth[4][DD*DD];    // transposed weights hi [N,K]
__device__ float g_E[BSD];
__device__ float g_O[BSD];

// ---------------- helpers ----------------------------------------------------
__device__ __forceinline__ uint32_t smem_u32(const void* p) {
    uint32_t a;
    asm("{ .reg .u64 t; cvta.to.shared.u64 t, %1; cvt.u32.u64 %0, t; }" : "=r"(a) : "l"(p));
    return a;
}
__device__ __forceinline__ float ex2(float x) {
    float y; asm("ex2.approx.f32 %0, %1;" : "=f"(y) : "f"(x)); return y;
}

#define SW128(off) ((off) ^ (((off) >> 3) & 0x70))

#define CP16(dst, src) \
    asm volatile("cp.async.cg.shared.global [%0], [%1], 16;" \
        :: "r"(dst), "l"(__cvta_generic_to_global(src)) : "memory")

#define LDSM_X4(r, a) \
    asm volatile("ldmatrix.sync.aligned.m8n8.x4.shared.b16 {%0,%1,%2,%3}, [%4];" \
        : "=r"((r)[0]), "=r"((r)[1]), "=r"((r)[2]), "=r"((r)[3]) : "r"(a))

#define LDSM_X4T(r, a) \
    asm volatile("ldmatrix.sync.aligned.m8n8.x4.trans.shared.b16 {%0,%1,%2,%3}, [%4];" \
        : "=r"((r)[0]), "=r"((r)[1]), "=r"((r)[2]), "=r"((r)[3]) : "r"(a))

#define MMA16816(c, a, b0, b1) \
    asm volatile("mma.sync.aligned.m16n8k16.row.col.f32.f16.f16.f32 " \
        "{%0,%1,%2,%3}, {%4,%5,%6,%7}, {%8,%9}, {%0,%1,%2,%3};" \
        : "+f"((c)[0]), "+f"((c)[1]), "+f"((c)[2]), "+f"((c)[3]) \
        : "r"((a)[0]), "r"((a)[1]), "r"((a)[2]), "r"((a)[3]), "r"(b0), "r"(b1))

__device__ __forceinline__ uint32_t pk2h(fp16 a, fp16 b) {
    __half2 t = __halves2half2(a, b);
    return *reinterpret_cast<uint32_t*>(&t);
}
__device__ __forceinline__ void split1(float v, fp16 &h, fp16 &l) {
    h = __float2half_rn(v);
    l = __float2half_rn(v - __half2float(h));
}

// ---------------- small kernels ---------------------------------------------
__global__ void split_x(const float4* __restrict__ in, uint2* __restrict__ hi,
                        uint2* __restrict__ lo, int n4) {
    int i = blockIdx.x * blockDim.x + threadIdx.x;
    int st = gridDim.x * blockDim.x;
    for (; i < n4; i += st) {
        float4 v = in[i];
        fp16 h0,h1,h2,h3,l0,l1,l2,l3;
        split1(v.x,h0,l0); split1(v.y,h1,l1); split1(v.z,h2,l2); split1(v.w,h3,l3);
        hi[i] = make_uint2(pk2h(h0,h1), pk2h(h2,h3));
        lo[i] = make_uint2(pk2h(l0,l1), pk2h(l2,l3));
    }
}

// final = (E + O) * countscale -> fp16 hi only (fin GEMM is single-pass now)
__global__ void combine_h(const float4* __restrict__ E, const float4* __restrict__ O,
                          uint2* __restrict__ hi, int n4) {
    int i = blockIdx.x * blockDim.x + threadIdx.x;
    int st = gridDim.x * blockDim.x;
    for (; i < n4; i += st) {
        int s = (i >> 8) & (SS - 1);
        bool edge = (s < 64) || (s >= SS - 64);
        float4 e = E[i];
        float4 o = edge ? make_float4(0.f,0.f,0.f,0.f) : O[i];
        float sc = edge ? 1.f : 0.5f;
        hi[i] = make_uint2(
            pk2h(__float2half_rn((e.x+o.x)*sc), __float2half_rn((e.y+o.y)*sc)),
            pk2h(__float2half_rn((e.z+o.z)*sc), __float2half_rn((e.w+o.w)*sc)));
    }
}

// 4 weight transposes in one launch: W[K,N] fp32 -> Wt[N,K] fp16 (z = which W)
__global__ void transpose_h4(const float* __restrict__ W0, const float* __restrict__ W1,
                             const float* __restrict__ W2, const float* __restrict__ W3,
                             fp16* __restrict__ hi) {
    __shared__ float tl[32][33];
    const float* W = (blockIdx.z == 0) ? W0 : (blockIdx.z == 1) ? W1
                   : (blockIdx.z == 2) ? W2 : W3;
    fp16* out = hi + (long)blockIdx.z * DD * DD;
    int bx = blockIdx.x * 32, by = blockIdx.y * 32;
    int tx = threadIdx.x, ty = threadIdx.y;
#pragma unroll
    for (int r = 0; r < 32; r += 8)
        tl[ty + r][tx] = W[(long)(by + ty + r) * DD + bx + tx];
    __syncthreads();
#pragma unroll
    for (int r = 0; r < 32; r += 8)
        out[(long)(bx + ty + r) * DD + by + tx] = __float2half_rn(tl[tx][ty + r]);
}

// ---------------- shared GEMM constants ---------------------------------------
// Warp grid 4x2, warp tile 32x64: 8 LDSM per 32 MMA.
#define GEMM_SMEM 98304
#define FIN_SMEM  65536

// ---------------- merged QKV GEMM: gridDim.z = 3 selects Q/K/V ---------------
// Q (which==0): 2 passes (Ah+Al). K/V: 1 pass (outputs fp16-rounded anyway).
__global__ void __launch_bounds__(256, 2) gemm_qkv(
    const fp16* __restrict__ Ah, const fp16* __restrict__ Al,
    const fp16* __restrict__ Wt,
    const float* __restrict__ bq, const float* __restrict__ bk,
    const float* __restrict__ bv,
    fp16* __restrict__ Qhi, fp16* __restrict__ Qlo,
    fp16* __restrict__ Khi, fp16* __restrict__ Vhi)
{
    extern __shared__ char smem[];
    const uint32_t sb = smem_u32(smem);
    const int t = threadIdx.x;
    const int lane = t & 31, wid = t >> 5;
    const int wrow = wid & 3;
    const int wcol = wid >> 2;
    const int which = blockIdx.z;
    const long m0 = (long)blockIdx.y * 128;
    const int  n0 = blockIdx.x * 128;
    const fp16* Bh = Wt + (long)which * DD * DD;
    const int npass = (which == 0) ? 2 : 1;

    const uint32_t sAh[2] = { sb,         sb + 16384 };
    const uint32_t sAl[2] = { sb + 32768, sb + 49152 };
    const uint32_t sB[2]  = { sb + 65536, sb + 81920 };

    int rowg[4]; uint32_t dsts[4];
#pragma unroll
    for (int i = 0; i < 4; i++) {
        int u = t + 256 * i;
        rowg[i] = u >> 3;
        dsts[i] = SW128((u >> 3) * 128 + (u & 7) * 16);
    }
    const int kcol8 = (t & 7) * 8;

    uint32_t a_rowoff[2], a_swz[2];
#pragma unroll
    for (int ms = 0; ms < 2; ms++) {
        int row = wrow * 32 + ms * 16 + (lane & 15);
        a_rowoff[ms] = row * 128;
        a_swz[ms]    = (row & 7) * 16;
    }
    const uint32_t a_kext = (lane >> 4) * 16;
    uint32_t b_rowoff[4], b_swz[4];
#pragma unroll
    for (int np = 0; np < 4; np++) {
        int row = wcol * 64 + np * 16 + ((lane >> 4) & 1) * 8 + (lane & 7);
        b_rowoff[np] = row * 128;
        b_swz[np]    = (row & 7) * 16;
    }
    const uint32_t b_kext = ((lane >> 3) & 1) * 16;

    float acc[2][8][4];
#pragma unroll
    for (int i = 0; i < 2; i++)
#pragma unroll
        for (int j = 0; j < 8; j++)
#pragma unroll
            for (int r = 0; r < 4; r++) acc[i][j][r] = 0.f;

    auto load_chunk = [&](int c, int buf) {
        int kc = c * 64;
        const fp16* Abh = Ah + kc + kcol8;
        const fp16* Bb  = Bh + kc + kcol8;
#pragma unroll
        for (int i = 0; i < 4; i++) CP16(sAh[buf] + dsts[i], Abh + (m0 + rowg[i]) * DD);
        if (which == 0) {
            const fp16* Abl = Al + kc + kcol8;
#pragma unroll
            for (int i = 0; i < 4; i++) CP16(sAl[buf] + dsts[i], Abl + (m0 + rowg[i]) * DD);
        }
#pragma unroll
        for (int i = 0; i < 4; i++) CP16(sB[buf]  + dsts[i], Bb  + (long)(n0 + rowg[i]) * DD);
        asm volatile("cp.async.commit_group;" ::: "memory");
    };

    load_chunk(0, 0);

    for (int c = 0; c < 16; c++) {
        const int buf = c & 1;
        asm volatile("cp.async.wait_group 0;" ::: "memory");
        __syncthreads();
        if (c + 1 < 16) load_chunk(c + 1, buf ^ 1);

#pragma unroll
        for (int k16 = 0; k16 < 4; k16++) {
            const uint32_t kb = k16 * 32;
            uint32_t bfr[4][4];
#pragma unroll
            for (int np = 0; np < 4; np++)
                LDSM_X4(bfr[np], sB[buf] + b_rowoff[np] + ((kb + b_kext) ^ b_swz[np]));
            for (int pass = 0; pass < npass; pass++) {
                const uint32_t bA = pass ? sAl[buf] : sAh[buf];
                uint32_t afr[2][4];
#pragma unroll
                for (int ms = 0; ms < 2; ms++)
                    LDSM_X4(afr[ms], bA + a_rowoff[ms] + ((kb + a_kext) ^ a_swz[ms]));
#pragma unroll
                for (int ms = 0; ms < 2; ms++)
#pragma unroll
                    for (int ns = 0; ns < 8; ns++)
                        MMA16816(acc[ms][ns], afr[ms],
                                 bfr[ns >> 1][(ns & 1) * 2], bfr[ns >> 1][(ns & 1) * 2 + 1]);
            }
        }
    }

    const float* bias = (which == 0) ? bq : (which == 1) ? bk : bv;
#pragma unroll
    for (int ms = 0; ms < 2; ms++) {
        long r0 = m0 + wrow * 32 + ms * 16 + (lane >> 2);
#pragma unroll
        for (int ns = 0; ns < 8; ns++) {
            int col = n0 + wcol * 64 + ns * 8 + (lane & 3) * 2;
            float2 bvv = *(const float2*)(bias + col);
            float v00 = acc[ms][ns][0] + bvv.x, v01 = acc[ms][ns][1] + bvv.y;
            float v10 = acc[ms][ns][2] + bvv.x, v11 = acc[ms][ns][3] + bvv.y;
            if (which == 0) {
                fp16 h0,h1,l0,l1;
                split1(v00, h0, l0); split1(v01, h1, l1);
                *(uint32_t*)(Qhi + r0 * DD + col) = pk2h(h0, h1);
                *(uint32_t*)(Qlo + r0 * DD + col) = pk2h(l0, l1);
                split1(v10, h0, l0); split1(v11, h1, l1);
                *(uint32_t*)(Qhi + (r0 + 8) * DD + col) = pk2h(h0, h1);
                *(uint32_t*)(Qlo + (r0 + 8) * DD + col) = pk2h(l0, l1);
            } else {
                fp16* dst = (which == 1) ? Khi : Vhi;
                *(uint32_t*)(dst + r0 * DD + col) =
                    pk2h(__float2half_rn(v00), __float2half_rn(v01));
                *(uint32_t*)(dst + (r0 + 8) * DD + col) =
                    pk2h(__float2half_rn(v10), __float2half_rn(v11));
            }
        }
    }
}

// ---------------- final AO GEMM (single pass: Ah only, fp32 out + bias) ------
__global__ void __launch_bounds__(256, 2) gemm_fin(
    const fp16* __restrict__ Ah, const fp16* __restrict__ Bh,
    const float* __restrict__ bias, float* __restrict__ C)
{
    extern __shared__ char smem[];
    const uint32_t sb = smem_u32(smem);
    const int t = threadIdx.x;
    const int lane = t & 31, wid = t >> 5;
    const int wrow = wid & 3;
    const int wcol = wid >> 2;
    const long m0 = (long)blockIdx.y * 128;
    const int  n0 = blockIdx.x * 128;

    const uint32_t sAh[2] = { sb,         sb + 16384 };
    const uint32_t sB[2]  = { sb + 32768, sb + 49152 };

    int rowg[4]; uint32_t dsts[4];
#pragma unroll
    for (int i = 0; i < 4; i++) {
        int u = t + 256 * i;
        rowg[i] = u >> 3;
        dsts[i] = SW128((u >> 3) * 128 + (u & 7) * 16);
    }
    const int kcol8 = (t & 7) * 8;

    uint32_t a_rowoff[2], a_swz[2];
#pragma unroll
    for (int ms = 0; ms < 2; ms++) {
        int row = wrow * 32 + ms * 16 + (lane & 15);
        a_rowoff[ms] = row * 128;
        a_swz[ms]    = (row & 7) * 16;
    }
    const uint32_t a_kext = (lane >> 4) * 16;
    uint32_t b_rowoff[4], b_swz[4];
#pragma unroll
    for (int np = 0; np < 4; np++) {
        int row = wcol * 64 + np * 16 + ((lane >> 4) & 1) * 8 + (lane & 7);
        b_rowoff[np] = row * 128;
        b_swz[np]    = (row & 7) * 16;
    }
    const uint32_t b_kext = ((lane >> 3) & 1) * 16;

    float acc[2][8][4];
#pragma unroll
    for (int i = 0; i < 2; i++)
#pragma unroll
        for (int j = 0; j < 8; j++)
#pragma unroll
            for (int r = 0; r < 4; r++) acc[i][j][r] = 0.f;

    auto load_chunk = [&](int c, int buf) {
        int kc = c * 64;
        const fp16* Ab = Ah + kc + kcol8;
        const fp16* Bb = Bh + kc + kcol8;
#pragma unroll
        for (int i = 0; i < 4; i++) CP16(sAh[buf] + dsts[i], Ab + (m0 + rowg[i]) * DD);
#pragma unroll
        for (int i = 0; i < 4; i++) CP16(sB[buf]  + dsts[i], Bb + (long)(n0 + rowg[i]) * DD);
        asm volatile("cp.async.commit_group;" ::: "memory");
    };

    load_chunk(0, 0);

    for (int c = 0; c < 16; c++) {
        const int buf = c & 1;
        asm volatile("cp.async.wait_group 0;" ::: "memory");
        __syncthreads();
        if (c + 1 < 16) load_chunk(c + 1, buf ^ 1);

#pragma unroll
        for (int k16 = 0; k16 < 4; k16++) {
            const uint32_t kb = k16 * 32;
            uint32_t bfr[4][4];
#pragma unroll
            for (int np = 0; np < 4; np++)
                LDSM_X4(bfr[np], sB[buf] + b_rowoff[np] + ((kb + b_kext) ^ b_swz[np]));
            uint32_t afr[2][4];
#pragma unroll
            for (int ms = 0; ms < 2; ms++)
                LDSM_X4(afr[ms], sAh[buf] + a_rowoff[ms] + ((kb + a_kext) ^ a_swz[ms]));
#pragma unroll
            for (int ms = 0; ms < 2; ms++)
#pragma unroll
                for (int ns = 0; ns < 8; ns++)
                    MMA16816(acc[ms][ns], afr[ms],
                             bfr[ns >> 1][(ns & 1) * 2], bfr[ns >> 1][(ns & 1) * 2 + 1]);
        }
    }

#pragma unroll
    for (int ms = 0; ms < 2; ms++) {
        long r0 = m0 + wrow * 32 + ms * 16 + (lane >> 2);
#pragma unroll
        for (int ns = 0; ns < 8; ns++) {
            int col = n0 + wcol * 64 + ns * 8 + (lane & 3) * 2;
            float2 bv = *(const float2*)(bias + col);
            *(float2*)(C + r0 * DD + col) =
                make_float2(acc[ms][ns][0] + bv.x, acc[ms][ns][1] + bv.y);
            *(float2*)(C + (r0 + 8) * DD + col) =
                make_float2(acc[ms][ns][2] + bv.x, acc[ms][ns][3] + bv.y);
        }
    }
}

// ---------------- windowed attention (R13-proven form, FROZEN) ---------------
#define ATT_PHI   32768
#define ATT_PLO   65536
#define ATT_RED   98304
#define ATT_SMEM  100352

__global__ void __launch_bounds__(256, 2) window_attn_mma(
    const fp16* __restrict__ qh, const fp16* __restrict__ ql,
    const fp16* __restrict__ kh, const fp16* __restrict__ vh,
    float* __restrict__ Ebuf, float* __restrict__ Obuf)
{
    extern __shared__ char smem[];
    const uint32_t sb = smem_u32(smem);
    const int t = threadIdx.x;
    const int lane = t & 31, wid = t >> 5;
    const int wrow = wid & 1;
    const int wcol = wid >> 1;
    const int w = blockIdx.x, b = blockIdx.y;
    const long qbase = ((long)b * SS + w * 64) * DD;

    const uint32_t sQh[2] = { sb,         sb + 16384 };
    const uint32_t sQl[2] = { sb + 32768, sb + 49152 };
    const uint32_t sK[2]  = { sb + 65536, sb + 81920 };
    const uint32_t vbf[2] = { sb,         sb + 16384 };

    int rowg[4]; uint32_t dsts[4];
#pragma unroll
    for (int i = 0; i < 4; i++) {
        int u = t + 256 * i;
        rowg[i] = u >> 3;
        dsts[i] = SW128((u >> 3) * 128 + (u & 7) * 16);
    }
    const int kcol8 = (t & 7) * 8;

    uint32_t a_rowoff[4], a_swz[4];
#pragma unroll
    for (int ms = 0; ms < 4; ms++) {
        int row = wrow * 64 + ms * 16 + (lane & 15);
        a_rowoff[ms] = row * 128;
        a_swz[ms]    = (row & 7) * 16;
    }
    const uint32_t a_kext = (lane >> 4) * 16;
    uint32_t b_rowoff[2], b_swz[2];
#pragma unroll
    for (int np = 0; np < 2; np++) {
        int row = wcol * 32 + np * 16 + ((lane >> 4) & 1) * 8 + (lane & 7);
        b_rowoff[np] = row * 128;
        b_swz[np]    = (row & 7) * 16;
    }
    const uint32_t b_kext = ((lane >> 3) & 1) * 16;

    float acc[4][4][4];
#pragma unroll
    for (int i = 0; i < 4; i++)
#pragma unroll
        for (int j = 0; j < 4; j++)
#pragma unroll
            for (int r = 0; r < 4; r++) acc[i][j][r] = 0.f;

    auto load_qk = [&](int c, int buf) {
        int kc = c * 64;
        const fp16* Abh = qh + qbase + kc + kcol8;
        const fp16* Abl = ql + qbase + kc + kcol8;
        const fp16* Bb  = kh + qbase + kc + kcol8;
#pragma unroll
        for (int i = 0; i < 4; i++) CP16(sQh[buf] + dsts[i], Abh + (long)rowg[i] * DD);
#pragma unroll
        for (int i = 0; i < 4; i++) CP16(sQl[buf] + dsts[i], Abl + (long)rowg[i] * DD);
#pragma unroll
        for (int i = 0; i < 4; i++) CP16(sK[buf]  + dsts[i], Bb  + (long)rowg[i] * DD);
        asm volatile("cp.async.commit_group;" ::: "memory");
    };

    load_qk(0, 0);

    for (int c = 0; c < 16; c++) {
        const int buf = c & 1;
        asm volatile("cp.async.wait_group 0;" ::: "memory");
        __syncthreads();
        if (c + 1 < 16) load_qk(c + 1, buf ^ 1);

#pragma unroll
        for (int k16 = 0; k16 < 4; k16++) {
            const uint32_t kb = k16 * 32;
            uint32_t bfr[2][4];
#pragma unroll
            for (int np = 0; np < 2; np++)
                LDSM_X4(bfr[np], sK[buf] + b_rowoff[np] + ((kb + b_kext) ^ b_swz[np]));
#pragma unroll
            for (int pass = 0; pass < 2; pass++) {
                const uint32_t bA = pass ? sQl[buf] : sQh[buf];
                uint32_t afr[4][4];
#pragma unroll
                for (int ms = 0; ms < 4; ms++)
                    LDSM_X4(afr[ms], bA + a_rowoff[ms] + ((kb + a_kext) ^ a_swz[ms]));
#pragma unroll
                for (int ms = 0; ms < 4; ms++)
#pragma unroll
                    for (int ns = 0; ns < 4; ns++)
                        MMA16816(acc[ms][ns], afr[ms],
                                 bfr[ns >> 1][(ns & 1) * 2], bfr[ns >> 1][(ns & 1) * 2 + 1]);
            }
        }
    }

    auto load_v = [&](int nc, int buf) {
        const fp16* Vh = vh + qbase + nc * 64 + kcol8;
#pragma unroll
        for (int i = 0; i < 4; i++) CP16(vbf[buf] + dsts[i], Vh + (long)rowg[i] * DD);
        asm volatile("cp.async.commit_group;" ::: "memory");
    };
    load_v(0, 0);

    const float CEXP = 0.1803368801f;
    float* red = (float*)(smem + ATT_RED);
    float ps[4][2];
#pragma unroll
    for (int ms = 0; ms < 4; ms++) {
        ps[ms][0] = 0.f; ps[ms][1] = 0.f;
#pragma unroll
        for (int ns = 0; ns < 4; ns++) {
#pragma unroll
            for (int r = 0; r < 4; r++) {
                float e = ex2(acc[ms][ns][r] * CEXP);
                acc[ms][ns][r] = e;
                ps[ms][r >> 1] += e;
            }
        }
    }
#pragma unroll
    for (int off = 1; off < 4; off <<= 1)
#pragma unroll
        for (int ms = 0; ms < 4; ms++) {
            ps[ms][0] += __shfl_xor_sync(0xffffffffu, ps[ms][0], off);
            ps[ms][1] += __shfl_xor_sync(0xffffffffu, ps[ms][1], off);
        }
    if ((lane & 3) == 0) {
#pragma unroll
        for (int ms = 0; ms < 4; ms++)
#pragma unroll
            for (int h = 0; h < 2; h++) {
                int row = wrow * 64 + ms * 16 + (lane >> 2) + h * 8;
                red[wcol * 128 + row] = ps[ms][h];
            }
    }
    __syncthreads();

#pragma unroll
    for (int ms = 0; ms < 4; ms++) {
#pragma unroll
        for (int h = 0; h < 2; h++) {
            int row = wrow * 64 + ms * 16 + (lane >> 2) + h * 8;
            float s = red[row] + red[128 + row] + red[256 + row] + red[384 + row];
            float inv = 1.f / s;
#pragma unroll
            for (int ns = 0; ns < 4; ns++) {
                int col = wcol * 32 + ns * 8 + (lane & 3) * 2;
                float p0 = acc[ms][ns][h * 2]     * inv;
                float p1 = acc[ms][ns][h * 2 + 1] * inv;
                fp16 h0, l0, h1, l1;
                split1(p0, h0, l0); split1(p1, h1, l1);
                uint32_t off = (col >> 6) * 16384 + SW128(row * 128 + (col & 63) * 2);
                *(uint32_t*)(smem + ATT_PHI + off) = pk2h(h0, h1);
                *(uint32_t*)(smem + ATT_PLO + off) = pk2h(l0, l1);
            }
        }
    }
    __syncthreads();

    const int r0v = (lane & 7) + ((lane >> 3) & 1) * 8;
    const uint32_t b2_row = (uint32_t)r0v * 128;
    const uint32_t b2_cs  = ((wcol * 16 + (lane >> 4) * 8) * 2) ^ ((r0v & 7) * 16);

    float* dst = (w & 1) ? Obuf : Ebuf;
    const long rowbase = (long)b * SS + w * 64 + wrow * 64;

    for (int nc = 0; nc < 16; nc++) {
        const int buf = nc & 1;
        asm volatile("cp.async.wait_group 0;" ::: "memory");
        __syncthreads();
        if (nc + 1 < 16) load_v(nc + 1, buf ^ 1);

        float acc2[4][2][4];
#pragma unroll
        for (int i = 0; i < 4; i++)
#pragma unroll
            for (int j = 0; j < 2; j++)
#pragma unroll
                for (int r = 0; r < 4; r++) acc2[i][j][r] = 0.f;

#pragma unroll
        for (int k16 = 0; k16 < 8; k16++) {
            const uint32_t pchunk = (k16 >> 2) * 16384;
            const uint32_t kb = (k16 & 3) * 32;
            uint32_t bfr[4];
            LDSM_X4T(bfr, vbf[buf] + b2_row + (uint32_t)k16 * 2048 + b2_cs);
#pragma unroll
            for (int pass = 0; pass < 2; pass++) {
                const uint32_t Pb = sb + (pass ? ATT_PLO : ATT_PHI);
                uint32_t afr[4][4];
#pragma unroll
                for (int ms = 0; ms < 4; ms++)
                    LDSM_X4(afr[ms], Pb + pchunk + a_rowoff[ms] + ((kb + a_kext) ^ a_swz[ms]));
#pragma unroll
                for (int ms = 0; ms < 4; ms++) {
                    MMA16816(acc2[ms][0], afr[ms], bfr[0], bfr[1]);
                    MMA16816(acc2[ms][1], afr[ms], bfr[2], bfr[3]);
                }
            }
        }

#pragma unroll
        for (int ms = 0; ms < 4; ms++) {
#pragma unroll
            for (int h = 0; h < 2; h++) {
                long s = rowbase + ms * 16 + (lane >> 2) + h * 8;
#pragma unroll
                for (int ns = 0; ns < 2; ns++) {
                    int col = nc * 64 + wcol * 16 + ns * 8 + (lane & 3) * 2;
                    *(float2*)(dst + s * DD + col) =
                        make_float2(acc2[ms][ns][h * 2], acc2[ms][ns][h * 2 + 1]);
                }
            }
        }
    }
}

// ---------------- launch -----------------------------------------------------
extern "C" void kernel_launch(void* const* d_in, const int* in_sizes, int n_in,
                              void* d_out, int out_size)
{
    const float* x  = (const float*)d_in[0];
    const float* Wq = (const float*)d_in[1];
    const float* bq = (const float*)d_in[2];
    const float* Wk = (const float*)d_in[3];
    const float* bk = (const float*)d_in[4];
    const float* Wv = (const float*)d_in[5];
    const float* bv = (const float*)d_in[6];
    const float* Wo = (const float*)d_in[7];
    const float* bo = (const float*)d_in[8];
    float* out = (float*)d_out;

    fp16 *qh,*ql,*kh,*vh,*xh,*xl,*ah,*wth;
    float *E, *O;
    cudaGetSymbolAddress((void**)&qh, g_qh); cudaGetSymbolAddress((void**)&ql, g_ql);
    cudaGetSymbolAddress((void**)&kh, g_kh);
    cudaGetSymbolAddress((void**)&vh, g_vh);
    cudaGetSymbolAddress((void**)&xh, g_xh); cudaGetSymbolAddress((void**)&xl, g_xl);
    cudaGetSymbolAddress((void**)&ah, g_ah);
    cudaGetSymbolAddress((void**)&wth, g_wth);
    cudaGetSymbolAddress((void**)&E, g_E); cudaGetSymbolAddress((void**)&O, g_O);

    cudaFuncSetAttribute(gemm_qkv, cudaFuncAttributeMaxDynamicSharedMemorySize, GEMM_SMEM);
    cudaFuncSetAttribute(gemm_fin, cudaFuncAttributeMaxDynamicSharedMemorySize, FIN_SMEM);
    cudaFuncSetAttribute(window_attn_mma, cudaFuncAttributeMaxDynamicSharedMemorySize, ATT_SMEM);

    transpose_h4<<<dim3(32, 32, 4), dim3(32, 8)>>>(Wq, Wk, Wv, Wo, wth);
    split_x<<<2048, 256>>>((const float4*)x, (uint2*)xh, (uint2*)xl, BSD / 4);

    gemm_qkv<<<dim3(DD / 128, MM / 128, 3), 256, GEMM_SMEM>>>(
        xh, xl, wth, bq, bk, bv, qh, ql, kh, vh);

    window_attn_mma<<<dim3(NW, BB), 256, ATT_SMEM>>>(qh, ql, kh, vh, E, O);

    combine_h<<<2048, 256>>>((const float4*)E, (const float4*)O, (uint2*)ah, BSD / 4);
    gemm_fin<<<dim3(DD / 128, MM / 128), 256, FIN_SMEM>>>(ah, wth + 3L*DD*DD, bo, out);
}